// round 4
// baseline (speedup 1.0000x reference)
// CrossVit_45148696216621 — full self-attention block, fp32 SIMT baseline.
//
// Pipeline (all multiples of 128, no bounds checks needed):
//   1. Q = x@Wq + bq, K = x@Wk + bk, V = x@Wv + bv      (3x GEMM_NN 8192x2048x2048)
//   2. S = Q @ K^T * (1/sqrt(2048))                      (GEMM_NT 8192x8192x2048)
//   3. rowwise softmax(S)                                (memory-bound, row fits in smem)
//   4. out = S @ V                                       (GEMM_NN 8192x2048x8192)
//
// Scratch via __device__ globals (sanctioned; no allocations anywhere).

#include <cuda_runtime.h>
#include <math.h>

#define SEQ 8192
#define EMB 2048

// ---------------------------------------------------------------------------
// Scratch (zero-init .bss-style device globals; ~448 MB total)
// ---------------------------------------------------------------------------
__device__ float g_Q[(size_t)SEQ * EMB];
__device__ float g_K[(size_t)SEQ * EMB];
__device__ float g_V[(size_t)SEQ * EMB];
__device__ float g_S[(size_t)SEQ * SEQ];

// ---------------------------------------------------------------------------
// SGEMM: C[M,N] = alpha * A[M,K] @ op(B) + bias
//   TB=false: B is [K,N] row-major (NN)
//   TB=true : B is [N,K] row-major (NT, i.e. C = A @ B^T)
// Block tile 128x128, K-tile 8, 256 threads, 8x8 per-thread micro-tile.
// M,N,K must be multiples of 128 / 8 (true for all call sites).
// ---------------------------------------------------------------------------
template <bool TB>
__global__ __launch_bounds__(256, 2)
void sgemm_kernel(const float* __restrict__ A,
                  const float* __restrict__ B,
                  float* __restrict__ C,
                  int M, int N, int K,
                  const float* __restrict__ bias,
                  float alpha)
{
    __shared__ float As[8][128];   // As[k][m]
    __shared__ float Bs[8][128];   // Bs[k][n]

    const int tid = threadIdx.x;
    const int bx = blockIdx.x;     // N-tile index
    const int by = blockIdx.y;     // M-tile index

    const int ty = tid >> 4;       // 0..15  -> micro-tile row group
    const int tx = tid & 15;       // 0..15  -> micro-tile col group

    float acc[8][8];
#pragma unroll
    for (int i = 0; i < 8; i++)
#pragma unroll
        for (int j = 0; j < 8; j++) acc[i][j] = 0.0f;

    // A tile loader: each thread loads one float4.
    // row = tid>>1 (0..127), k-col = (tid&1)*4
    const int aRow = tid >> 1;
    const int aCol = (tid & 1) * 4;
    const float* Aptr = A + (size_t)(by * 128 + aRow) * K + aCol;

    // B tile loader
    int bRow, bCol;
    const float* Bptr;
    if (TB) {
        // B is [N,K]: load like A (row = n within tile, col = k)
        bRow = tid >> 1;            // 0..127 (n)
        bCol = (tid & 1) * 4;       // k
        Bptr = B + (size_t)(bx * 128 + bRow) * K + bCol;
    } else {
        // B is [K,N]: 8 rows x 128 cols, row = k, col = n
        bRow = tid >> 5;            // 0..7 (k)
        bCol = (tid & 31) * 4;      // 0..124 (n)
        Bptr = B + (size_t)bRow * N + (size_t)bx * 128 + bCol;
    }

    for (int k0 = 0; k0 < K; k0 += 8) {
        // Global loads into registers first
        const float4 av = *(const float4*)(Aptr + k0);
        float4 bv;
        if (TB) bv = *(const float4*)(Bptr + k0);
        else    bv = *(const float4*)(Bptr + (size_t)k0 * N);

        __syncthreads();   // previous compute done before smem overwrite

        // Store A transposed: As[k][m]
        As[aCol + 0][aRow] = av.x;
        As[aCol + 1][aRow] = av.y;
        As[aCol + 2][aRow] = av.z;
        As[aCol + 3][aRow] = av.w;

        if (TB) {
            Bs[bCol + 0][bRow] = bv.x;
            Bs[bCol + 1][bRow] = bv.y;
            Bs[bCol + 2][bRow] = bv.z;
            Bs[bCol + 3][bRow] = bv.w;
        } else {
            *(float4*)&Bs[bRow][bCol] = bv;
        }

        __syncthreads();

#pragma unroll
        for (int kk = 0; kk < 8; kk++) {
            const float4 a0 = *(const float4*)&As[kk][ty * 8];
            const float4 a1 = *(const float4*)&As[kk][ty * 8 + 4];
            const float4 b0 = *(const float4*)&Bs[kk][tx * 8];
            const float4 b1 = *(const float4*)&Bs[kk][tx * 8 + 4];
            const float ar[8] = {a0.x, a0.y, a0.z, a0.w, a1.x, a1.y, a1.z, a1.w};
            const float br[8] = {b0.x, b0.y, b0.z, b0.w, b1.x, b1.y, b1.z, b1.w};
#pragma unroll
            for (int i = 0; i < 8; i++)
#pragma unroll
                for (int j = 0; j < 8; j++)
                    acc[i][j] = fmaf(ar[i], br[j], acc[i][j]);
        }
    }

    // Epilogue: alpha scale + optional bias, float4 stores
    const int row0 = by * 128 + ty * 8;
    const int col0 = bx * 128 + tx * 8;

    float bb[8];
#pragma unroll
    for (int j = 0; j < 8; j++) bb[j] = bias ? bias[col0 + j] : 0.0f;

#pragma unroll
    for (int i = 0; i < 8; i++) {
        float4 v0, v1;
        v0.x = acc[i][0] * alpha + bb[0];
        v0.y = acc[i][1] * alpha + bb[1];
        v0.z = acc[i][2] * alpha + bb[2];
        v0.w = acc[i][3] * alpha + bb[3];
        v1.x = acc[i][4] * alpha + bb[4];
        v1.y = acc[i][5] * alpha + bb[5];
        v1.z = acc[i][6] * alpha + bb[6];
        v1.w = acc[i][7] * alpha + bb[7];
        float* cptr = C + (size_t)(row0 + i) * N + col0;
        *(float4*)(cptr)     = v0;
        *(float4*)(cptr + 4) = v1;
    }
}

// ---------------------------------------------------------------------------
// Row-wise softmax over rows of length SEQ (8192 floats = 32 KB -> fits smem).
// One CTA (256 threads) per row. Numerically-stable (max-subtract).
// ---------------------------------------------------------------------------
__global__ __launch_bounds__(256)
void softmax_rows_kernel(float* __restrict__ S, int n)
{
    __shared__ float buf[SEQ];
    __shared__ float red[256];

    const int tid = threadIdx.x;
    float* p = S + (size_t)blockIdx.x * n;

    // Load row + local max
    float m = -INFINITY;
    for (int i = tid; i < n; i += 256) {
        const float v = p[i];
        buf[i] = v;
        m = fmaxf(m, v);
    }
    red[tid] = m;
    __syncthreads();
#pragma unroll
    for (int s = 128; s > 0; s >>= 1) {
        if (tid < s) red[tid] = fmaxf(red[tid], red[tid + s]);
        __syncthreads();
    }
    m = red[0];
    __syncthreads();   // everyone has read red[0] before reuse

    // exp + local sum
    float sum = 0.0f;
    for (int i = tid; i < n; i += 256) {
        const float e = expf(buf[i] - m);
        buf[i] = e;
        sum += e;
    }
    red[tid] = sum;
    __syncthreads();
#pragma unroll
    for (int s = 128; s > 0; s >>= 1) {
        if (tid < s) red[tid] += red[tid + s];
        __syncthreads();
    }
    const float inv = 1.0f / red[0];

    // Normalize + write back
    for (int i = tid; i < n; i += 256)
        p[i] = buf[i] * inv;
}

// ---------------------------------------------------------------------------
// Launch
// ---------------------------------------------------------------------------
extern "C" void kernel_launch(void* const* d_in, const int* in_sizes, int n_in,
                              void* d_out, int out_size)
{
    (void)in_sizes; (void)n_in; (void)out_size;

    const float* x  = (const float*)d_in[0];
    const float* Wq = (const float*)d_in[1];
    const float* bq = (const float*)d_in[2];
    const float* Wk = (const float*)d_in[3];
    const float* bk = (const float*)d_in[4];
    const float* Wv = (const float*)d_in[5];
    const float* bv = (const float*)d_in[6];
    float* out = (float*)d_out;

    // Resolve scratch symbol addresses once (cached -> capture call is
    // pure kernel launches; deterministic, no work skipped).
    static float *Qp = nullptr, *Kp = nullptr, *Vp = nullptr, *Sp = nullptr;
    if (!Qp) {
        cudaGetSymbolAddress((void**)&Qp, g_Q);
        cudaGetSymbolAddress((void**)&Kp, g_K);
        cudaGetSymbolAddress((void**)&Vp, g_V);
        cudaGetSymbolAddress((void**)&Sp, g_S);
    }

    const dim3 blk(256);
    const dim3 gProj(EMB / 128, SEQ / 128);   // (16, 64)
    const dim3 gScore(SEQ / 128, SEQ / 128);  // (64, 64)

    // 1. QKV projections (bias fused into epilogue)
    sgemm_kernel<false><<<gProj, blk>>>(x, Wq, Qp, SEQ, EMB, EMB, bq, 1.0f);
    sgemm_kernel<false><<<gProj, blk>>>(x, Wk, Kp, SEQ, EMB, EMB, bk, 1.0f);
    sgemm_kernel<false><<<gProj, blk>>>(x, Wv, Vp, SEQ, EMB, EMB, bv, 1.0f);

    // 2. S = Q @ K^T * 1/sqrt(EMB)
    const float scale = 1.0f / sqrtf((float)EMB);
    sgemm_kernel<true><<<gScore, blk>>>(Qp, Kp, Sp, SEQ, SEQ, EMB, nullptr, scale);

    // 3. softmax rows
    softmax_rows_kernel<<<SEQ, blk>>>(Sp, SEQ);

    // 4. out = P @ V
    sgemm_kernel<false><<<gProj, blk>>>(Sp, Vp, out, SEQ, EMB, SEQ, nullptr, 1.0f);
}